// round 3
// baseline (speedup 1.0000x reference)
#include <cuda_runtime.h>
#include <math.h>

// CSELoss: loss = -mean_i [ s(i,tgt) - log(sum_j exp(s(i,j))) ]
//   s(i,j) = 20 * dot(xn_i, xn_j), diagonal excluded (reference's -1e12 mask
//   makes exp() exactly 0 in fp32), tgt = i ^ 1.
// No max-subtraction needed: logits <= 20, row sums <= 8192*e^20 << FLT_MAX.

#define NROWS 8192
#define DD    128
#define AINV  20.0f   // 1/ALPHA

__device__ float g_xn[NROWS * DD];     // normalized embeddings (4 MB)
__device__ float g_rowsum[NROWS];      // sum_j exp(s_ij), j != i

// ---------------------------------------------------------------------------
__global__ void init_out_kernel(float* out) {
    if (threadIdx.x == 0) out[0] = 0.0f;
}

// One warp per row: sum of squares -> clamp(norm, 1e-8) -> scaled write.
__global__ void normalize_kernel(const float* __restrict__ in) {
    int w    = (blockIdx.x * blockDim.x + threadIdx.x) >> 5;
    int lane = threadIdx.x & 31;
    if (w >= NROWS) return;
    float4 v = ((const float4*)(in + (size_t)w * DD))[lane];
    float ss = v.x * v.x + v.y * v.y + v.z * v.z + v.w * v.w;
#pragma unroll
    for (int o = 16; o; o >>= 1) ss += __shfl_xor_sync(0xffffffffu, ss, o);
    float inv = 1.0f / fmaxf(sqrtf(ss), 1e-8f);
    v.x *= inv; v.y *= inv; v.z *= inv; v.w *= inv;
    ((float4*)(g_xn + (size_t)w * DD))[lane] = v;
}

// ---------------------------------------------------------------------------
// Fused GEMM + exp + row-sum.
// Grid: 128 CTAs, each owns a 64-row A tile (k-major in smem, resident) and
// sweeps all 8192 columns in 128-col B tiles. 256 threads as 16x16, each
// computing a 4x8 micro-tile via float4 smem reads.
#define BM 64
#define BN 128
#define AS_STRIDE 68    // pad: write stride 68 mod 32 = 4 (8-way, one-time load)
#define BS_STRIDE 132   // pad: keeps float4 alignment; writes are c-contiguous
#define TM 4
#define TN 8
#define NTHREADS 256

__global__ __launch_bounds__(NTHREADS, 1)
void expsum_kernel() {
    extern __shared__ float sm[];
    float* As = sm;                       // [DD][AS_STRIDE]
    float* Bs = sm + DD * AS_STRIDE;      // [DD][BS_STRIDE]
    __shared__ float rsum_s[BM];

    int tid = threadIdx.x;
    int tx  = tid & 15;
    int ty  = tid >> 4;
    int rowBase = blockIdx.x * BM;
    int r0 = ty * TM;
    int c0 = tx * TN;

    // Load A tile transposed: As[k][r] (one-time; coalesced gmem read).
    for (int idx = tid; idx < BM * DD; idx += NTHREADS) {
        int r = idx >> 7;        // idx / DD
        int k = idx & 127;       // idx % DD
        As[k * AS_STRIDE + r] = g_xn[(rowBase + r) * DD + k];
    }
    if (tid < BM) rsum_s[tid] = 0.0f;

    float rs[TM] = {0.f, 0.f, 0.f, 0.f};

    for (int ct = 0; ct < NROWS / BN; ct++) {
        int colBase = ct * BN;
        __syncthreads();   // also covers As/rsum_s init on first iteration
        // Load B tile: Bs[k][c]. c-fast mapping -> conflict-free smem writes.
        for (int idx = tid; idx < BN * DD / 4; idx += NTHREADS) {
            int c  = idx & 127;
            int k4 = idx >> 7;
            float4 v = *(const float4*)&g_xn[(colBase + c) * DD + k4 * 4];
            Bs[(k4 * 4 + 0) * BS_STRIDE + c] = v.x;
            Bs[(k4 * 4 + 1) * BS_STRIDE + c] = v.y;
            Bs[(k4 * 4 + 2) * BS_STRIDE + c] = v.z;
            Bs[(k4 * 4 + 3) * BS_STRIDE + c] = v.w;
        }
        __syncthreads();

        float acc[TM][TN];
#pragma unroll
        for (int i = 0; i < TM; i++)
#pragma unroll
            for (int j = 0; j < TN; j++) acc[i][j] = 0.0f;

#pragma unroll 8
        for (int k = 0; k < DD; k++) {
            float4 a  = *(const float4*)&As[k * AS_STRIDE + r0];
            float4 b0 = *(const float4*)&Bs[k * BS_STRIDE + c0];
            float4 b1 = *(const float4*)&Bs[k * BS_STRIDE + c0 + 4];
            float av[TM] = {a.x, a.y, a.z, a.w};
            float bv[TN] = {b0.x, b0.y, b0.z, b0.w, b1.x, b1.y, b1.z, b1.w};
#pragma unroll
            for (int i = 0; i < TM; i++)
#pragma unroll
                for (int j = 0; j < TN; j++)
                    acc[i][j] = fmaf(av[i], bv[j], acc[i][j]);
        }

        // Epilogue: exp + accumulate per-row, skip diagonal.
#pragma unroll
        for (int i = 0; i < TM; i++) {
            int gr = rowBase + r0 + i;
            float s = 0.0f;
#pragma unroll
            for (int j = 0; j < TN; j++) {
                int gc = colBase + c0 + j;
                float e = __expf(acc[i][j] * AINV);
                s += (gr != gc) ? e : 0.0f;
            }
            rs[i] += s;
        }
    }

    __syncthreads();
#pragma unroll
    for (int i = 0; i < TM; i++) atomicAdd(&rsum_s[r0 + i], rs[i]);
    __syncthreads();
    if (tid < BM) g_rowsum[rowBase + tid] = rsum_s[tid];
}

// ---------------------------------------------------------------------------
// One warp per row: target dot + log(rowsum), atomic mean into out[0].
__global__ void finalize_kernel(float* out) {
    int w    = (blockIdx.x * blockDim.x + threadIdx.x) >> 5;
    int lane = threadIdx.x & 31;
    if (w >= NROWS) return;
    int t = w ^ 1;
    float4 a = ((const float4*)(g_xn + (size_t)w * DD))[lane];
    float4 b = ((const float4*)(g_xn + (size_t)t * DD))[lane];
    float d = a.x * b.x + a.y * b.y + a.z * b.z + a.w * b.w;
#pragma unroll
    for (int o = 16; o; o >>= 1) d += __shfl_xor_sync(0xffffffffu, d, o);
    if (lane == 0) {
        float l = AINV * d - logf(g_rowsum[w]);
        atomicAdd(out, -l * (1.0f / NROWS));
    }
}

// ---------------------------------------------------------------------------
extern "C" void kernel_launch(void* const* d_in, const int* in_sizes, int n_in,
                              void* d_out, int out_size) {
    const float* in = (const float*)d_in[0];
    float* out = (float*)d_out;
    (void)in_sizes; (void)n_in; (void)out_size;

    size_t smem = (size_t)(DD * AS_STRIDE + DD * BS_STRIDE) * sizeof(float);
    // Idempotent, capture-safe (not a stream op). If it ever failed, the
    // subsequent launch would surface a clean config error via the harness.
    (void)cudaFuncSetAttribute(expsum_kernel,
                               cudaFuncAttributeMaxDynamicSharedMemorySize,
                               (int)smem);

    init_out_kernel<<<1, 32>>>(out);
    normalize_kernel<<<NROWS / 8, 256>>>(in);
    expsum_kernel<<<NROWS / BM, NTHREADS, smem>>>();
    finalize_kernel<<<NROWS / 8, 256>>>(out);
}

// round 5
// speedup vs baseline: 9.3749x; 9.3749x over previous
#include <cuda_runtime.h>
#include <cuda_bf16.h>
#include <math.h>
#include <cstdint>

// CSELoss: loss = -mean_i [ s(i,i^1) - log(sum_{j!=i} exp(s_ij)) ],
// s = (Xn Xn^T)/alpha.  GEMM+exp+rowsum fused, tensor cores via mma.sync
// (baseline PTX -- harness compiles at plain sm_100, no 'a' features).

#define NROWS 8192
#define DD    128
#define TILE  128
#define AINV  20.0f
#define NT    (NROWS / TILE)   // 64 tiles per dim
#define STRB  272              // smem row stride bytes (136 bf16): conflict-free ldmatrix

__device__ float          g_xn[NROWS * DD];   // fp32 normalized (finalize accuracy)
__device__ __nv_bfloat16  g_xb[NROWS * DD];   // bf16 normalized (MMA operands)
__device__ float          g_rowsum[NROWS];

// ---------------------------------------------------------------------------
__device__ __forceinline__ uint32_t smem_u32(const void* p) {
    uint32_t a;
    asm("{ .reg .u64 t; cvta.to.shared.u64 t, %1; cvt.u32.u64 %0, t; }" : "=r"(a) : "l"(p));
    return a;
}
__device__ __forceinline__ void ldm_x4(uint32_t& r0, uint32_t& r1, uint32_t& r2,
                                       uint32_t& r3, uint32_t addr) {
    asm volatile("ldmatrix.sync.aligned.m8n8.x4.shared.b16 {%0,%1,%2,%3}, [%4];"
                 : "=r"(r0), "=r"(r1), "=r"(r2), "=r"(r3) : "r"(addr));
}
__device__ __forceinline__ void mma16816(float* c, const uint32_t* a,
                                         uint32_t b0, uint32_t b1) {
    asm volatile("mma.sync.aligned.m16n8k16.row.col.f32.bf16.bf16.f32 "
                 "{%0,%1,%2,%3}, {%4,%5,%6,%7}, {%8,%9}, {%0,%1,%2,%3};"
                 : "+f"(c[0]), "+f"(c[1]), "+f"(c[2]), "+f"(c[3])
                 : "r"(a[0]), "r"(a[1]), "r"(a[2]), "r"(a[3]), "r"(b0), "r"(b1));
}

// ---------------------------------------------------------------------------
__global__ void zero_kernel(float* out) {
    int i = blockIdx.x * blockDim.x + threadIdx.x;
    if (i < NROWS) g_rowsum[i] = 0.0f;
    if (i == 0) out[0] = 0.0f;
}

__global__ void normalize_kernel(const float* __restrict__ in) {
    int w    = (blockIdx.x * blockDim.x + threadIdx.x) >> 5;
    int lane = threadIdx.x & 31;
    if (w >= NROWS) return;
    float4 v = ((const float4*)(in + (size_t)w * DD))[lane];
    float ss = v.x * v.x + v.y * v.y + v.z * v.z + v.w * v.w;
#pragma unroll
    for (int o = 16; o; o >>= 1) ss += __shfl_xor_sync(0xffffffffu, ss, o);
    float inv = 1.0f / fmaxf(sqrtf(ss), 1e-8f);
    v.x *= inv; v.y *= inv; v.z *= inv; v.w *= inv;
    ((float4*)(g_xn + (size_t)w * DD))[lane] = v;
    __nv_bfloat162* bb = (__nv_bfloat162*)(g_xb + (size_t)w * DD);
    bb[lane * 2 + 0] = __nv_bfloat162(__float2bfloat16_rn(v.x), __float2bfloat16_rn(v.y));
    bb[lane * 2 + 1] = __nv_bfloat162(__float2bfloat16_rn(v.z), __float2bfloat16_rn(v.w));
}

// ---------------------------------------------------------------------------
// One CTA = one 128x128 tile of S. 8 warps in 4(m) x 2(n); warp tile 32x64.
// Both operands K-major in smem; mma row.col computes A.B^T directly.
__global__ __launch_bounds__(256)
void expsum_mma_kernel() {
    extern __shared__ __align__(16) char sm[];
    char* pA = sm;                     // 128 rows * 272 B = 34816
    char* pB = sm + 128 * STRB;        // same
    __shared__ float rsum[TILE];

    int tid  = threadIdx.x;
    int lane = tid & 31;
    int wid  = tid >> 5;
    int warp_m = wid & 3;              // 0..3 -> 32-row block
    int warp_n = wid >> 2;             // 0..1 -> 64-col block
    int bi = blockIdx.x >> 6;
    int bj = blockIdx.x & (NT - 1);
    int rowBase = bi * TILE;
    int colBase = bj * TILE;

    // Load both tiles: 2048 16B-chunks each, coalesced (rows are 256B in gmem).
#pragma unroll
    for (int it = 0; it < 8; it++) {
        int chunk = tid + it * 256;          // 0..2047
        int r = chunk >> 4;
        int c = (chunk & 15) << 3;           // bf16 col
        *(uint4*)(pA + r * STRB + c * 2) =
            *(const uint4*)&g_xb[(size_t)(rowBase + r) * DD + c];
        *(uint4*)(pB + r * STRB + c * 2) =
            *(const uint4*)&g_xb[(size_t)(colBase + r) * DD + c];
    }
    if (tid < TILE) rsum[tid] = 0.0f;
    __syncthreads();

    // ldmatrix lane addressing: lanes 0-15 -> rows 0-15 at byte-col 0 (k0-7),
    // lanes 16-31 -> rows 0-15 at byte-col 16 (k8-15).
    uint32_t lrow = lane & 15;
    uint32_t lcol = (lane >> 4) << 4;
    uint32_t aAddr = smem_u32(pA) + (warp_m * 32 + lrow) * STRB + lcol;
    uint32_t bAddr = smem_u32(pB) + (warp_n * 64 + lrow) * STRB + lcol;

    float acc[2][8][4];
#pragma unroll
    for (int mf = 0; mf < 2; mf++)
#pragma unroll
        for (int nf = 0; nf < 8; nf++)
#pragma unroll
            for (int e = 0; e < 4; e++) acc[mf][nf][e] = 0.0f;

#pragma unroll
    for (int kk = 0; kk < 8; kk++) {
        uint32_t ka = kk * 32;               // 16 bf16 = 32 bytes per k-step
        uint32_t a[2][4];
        ldm_x4(a[0][0], a[0][1], a[0][2], a[0][3], aAddr + ka);
        ldm_x4(a[1][0], a[1][1], a[1][2], a[1][3], aAddr + 16 * STRB + ka);
        uint32_t br[4][4];
#pragma unroll
        for (int nb = 0; nb < 4; nb++)
            ldm_x4(br[nb][0], br[nb][1], br[nb][2], br[nb][3],
                   bAddr + nb * 16 * STRB + ka);
#pragma unroll
        for (int mf = 0; mf < 2; mf++)
#pragma unroll
            for (int nf = 0; nf < 8; nf++) {
                int nb = nf >> 1, odd = nf & 1;
                // n8k16 B frag: {k0-7, k8-15} = {r[odd], r[odd+2]}
                mma16816(acc[mf][nf], a[mf], br[nb][odd], br[nb][odd + 2]);
            }
    }

    // Epilogue: exp + row reduction. c-frag: lane holds rows q,(q+8), cols 2*rm,+1.
    int q = lane >> 2, rm = lane & 3;
#pragma unroll
    for (int mf = 0; mf < 2; mf++) {
        int r0  = warp_m * 32 + mf * 16 + q;
        int gr0 = rowBase + r0, gr1 = gr0 + 8;
        float s0 = 0.0f, s1 = 0.0f;
#pragma unroll
        for (int nf = 0; nf < 8; nf++) {
            int gc = colBase + warp_n * 64 + nf * 8 + rm * 2;
            float e;
            e = __expf(acc[mf][nf][0] * AINV); s0 += (gr0 != gc)     ? e : 0.0f;
            e = __expf(acc[mf][nf][1] * AINV); s0 += (gr0 != gc + 1) ? e : 0.0f;
            e = __expf(acc[mf][nf][2] * AINV); s1 += (gr1 != gc)     ? e : 0.0f;
            e = __expf(acc[mf][nf][3] * AINV); s1 += (gr1 != gc + 1) ? e : 0.0f;
        }
        s0 += __shfl_xor_sync(0xffffffffu, s0, 1);
        s0 += __shfl_xor_sync(0xffffffffu, s0, 2);
        s1 += __shfl_xor_sync(0xffffffffu, s1, 1);
        s1 += __shfl_xor_sync(0xffffffffu, s1, 2);
        if (rm == 0) {
            atomicAdd(&rsum[r0], s0);
            atomicAdd(&rsum[r0 + 8], s1);
        }
    }
    __syncthreads();
    if (tid < TILE) atomicAdd(&g_rowsum[rowBase + tid], rsum[tid]);
}

// ---------------------------------------------------------------------------
__global__ void finalize_kernel(float* out) {
    int w    = (blockIdx.x * blockDim.x + threadIdx.x) >> 5;
    int lane = threadIdx.x & 31;
    if (w >= NROWS) return;
    int t = w ^ 1;
    float4 a = ((const float4*)(g_xn + (size_t)w * DD))[lane];
    float4 b = ((const float4*)(g_xn + (size_t)t * DD))[lane];
    float d = a.x * b.x + a.y * b.y + a.z * b.z + a.w * b.w;
#pragma unroll
    for (int o = 16; o; o >>= 1) d += __shfl_xor_sync(0xffffffffu, d, o);
    if (lane == 0) {
        float l = AINV * d - logf(g_rowsum[w]);
        atomicAdd(out, -l * (1.0f / NROWS));
    }
}

// ---------------------------------------------------------------------------
extern "C" void kernel_launch(void* const* d_in, const int* in_sizes, int n_in,
                              void* d_out, int out_size) {
    const float* in = (const float*)d_in[0];
    float* out = (float*)d_out;
    (void)in_sizes; (void)n_in; (void)out_size;

    int dynBytes = 2 * 128 * STRB;   // 69632
    (void)cudaFuncSetAttribute(expsum_mma_kernel,
                               cudaFuncAttributeMaxDynamicSharedMemorySize,
                               dynBytes);

    zero_kernel<<<NROWS / 256, 256>>>(out);
    normalize_kernel<<<NROWS / 8, 256>>>(in);
    expsum_mma_kernel<<<NT * NT, 256, dynBytes>>>();
    finalize_kernel<<<NROWS / 8, 256>>>(out);
}

// round 6
// speedup vs baseline: 13.4352x; 1.4331x over previous
#include <cuda_runtime.h>
#include <cuda_bf16.h>
#include <math.h>
#include <cstdint>

// CSELoss: loss = -mean_i [ s(i,i^1) - log(sum_{j!=i} exp(s_ij)) ], s = Xn Xn^T / alpha.
// Symmetric: only upper-triangle tiles computed; each exp serves row- and col-sums.

#define NROWS 8192
#define DD    128
#define TILE  128
#define AINV  20.0f
#define NT    (NROWS / TILE)          // 64
#define NTILES (NT * (NT + 1) / 2)    // 2080
#define STRB  272                     // smem row stride bytes: conflict-free ldmatrix

__device__ float          g_xn[NROWS * DD];
__device__ __nv_bfloat16  g_xb[NROWS * DD];
__device__ float          g_rowsum[NROWS];
__device__ float          g_tdot[NROWS / 2];   // dot(x_{2p}, x_{2p+1}) normalized

// ---------------------------------------------------------------------------
__device__ __forceinline__ uint32_t smem_u32(const void* p) {
    uint32_t a;
    asm("{ .reg .u64 t; cvta.to.shared.u64 t, %1; cvt.u32.u64 %0, t; }" : "=r"(a) : "l"(p));
    return a;
}
__device__ __forceinline__ void ldm_x4(uint32_t& r0, uint32_t& r1, uint32_t& r2,
                                       uint32_t& r3, uint32_t addr) {
    asm volatile("ldmatrix.sync.aligned.m8n8.x4.shared.b16 {%0,%1,%2,%3}, [%4];"
                 : "=r"(r0), "=r"(r1), "=r"(r2), "=r"(r3) : "r"(addr));
}
__device__ __forceinline__ void mma16816(float* c, const uint32_t* a,
                                         uint32_t b0, uint32_t b1) {
    asm volatile("mma.sync.aligned.m16n8k16.row.col.f32.bf16.bf16.f32 "
                 "{%0,%1,%2,%3}, {%4,%5,%6,%7}, {%8,%9}, {%0,%1,%2,%3};"
                 : "+f"(c[0]), "+f"(c[1]), "+f"(c[2]), "+f"(c[3])
                 : "r"(a[0]), "r"(a[1]), "r"(a[2]), "r"(a[3]), "r"(b0), "r"(b1));
}

// ---------------------------------------------------------------------------
__global__ void zero_kernel(float* out) {
    int i = blockIdx.x * blockDim.x + threadIdx.x;
    if (i < NROWS) g_rowsum[i] = 0.0f;
    if (i == 0) out[0] = 0.0f;
}

// One warp per PAIR of rows: norms, normalized writes, and the pair dot.
__global__ void normalize_kernel(const float* __restrict__ in) {
    int p    = (blockIdx.x * blockDim.x + threadIdx.x) >> 5;   // pair index
    int lane = threadIdx.x & 31;
    if (p >= NROWS / 2) return;
    int r0 = p * 2;
    float4 v0 = ((const float4*)(in + (size_t)r0 * DD))[lane];
    float4 v1 = ((const float4*)(in + (size_t)(r0 + 1) * DD))[lane];
    float ss0 = v0.x*v0.x + v0.y*v0.y + v0.z*v0.z + v0.w*v0.w;
    float ss1 = v1.x*v1.x + v1.y*v1.y + v1.z*v1.z + v1.w*v1.w;
    float d   = v0.x*v1.x + v0.y*v1.y + v0.z*v1.z + v0.w*v1.w;
#pragma unroll
    for (int o = 16; o; o >>= 1) {
        ss0 += __shfl_xor_sync(0xffffffffu, ss0, o);
        ss1 += __shfl_xor_sync(0xffffffffu, ss1, o);
        d   += __shfl_xor_sync(0xffffffffu, d,   o);
    }
    float i0 = 1.0f / fmaxf(sqrtf(ss0), 1e-8f);
    float i1 = 1.0f / fmaxf(sqrtf(ss1), 1e-8f);
    v0.x *= i0; v0.y *= i0; v0.z *= i0; v0.w *= i0;
    v1.x *= i1; v1.y *= i1; v1.z *= i1; v1.w *= i1;
    ((float4*)(g_xn + (size_t)r0 * DD))[lane]       = v0;
    ((float4*)(g_xn + (size_t)(r0 + 1) * DD))[lane] = v1;
    __nv_bfloat162* b0 = (__nv_bfloat162*)(g_xb + (size_t)r0 * DD);
    __nv_bfloat162* b1 = (__nv_bfloat162*)(g_xb + (size_t)(r0 + 1) * DD);
    b0[lane*2+0] = __nv_bfloat162(__float2bfloat16_rn(v0.x), __float2bfloat16_rn(v0.y));
    b0[lane*2+1] = __nv_bfloat162(__float2bfloat16_rn(v0.z), __float2bfloat16_rn(v0.w));
    b1[lane*2+0] = __nv_bfloat162(__float2bfloat16_rn(v1.x), __float2bfloat16_rn(v1.y));
    b1[lane*2+1] = __nv_bfloat162(__float2bfloat16_rn(v1.z), __float2bfloat16_rn(v1.w));
    if (lane == 0) g_tdot[p] = d * i0 * i1;
}

// ---------------------------------------------------------------------------
// One CTA per upper-triangle tile (bi <= bj). 8 warps: 4(m) x 2(n), warp tile 32x64.
__global__ __launch_bounds__(256, 2)
void expsum_mma_kernel() {
    extern __shared__ __align__(16) char sm[];
    char* pA = sm;
    char* pB = sm + 128 * STRB;
    __shared__ float rsum[TILE];
    __shared__ float csum[TILE];

    int tid  = threadIdx.x;
    int lane = tid & 31;
    int wid  = tid >> 5;
    int warp_m = wid & 3;
    int warp_n = wid >> 2;

    // Linear tile index -> upper-triangle (bi, bj).
    int t = blockIdx.x, bi = 0;
    while (t >= NT - bi) { t -= NT - bi; bi++; }
    int bj = bi + t;
    bool diag = (bi == bj);
    int rowBase = bi * TILE;
    int colBase = bj * TILE;

#pragma unroll
    for (int it = 0; it < 8; it++) {
        int chunk = tid + it * 256;
        int r = chunk >> 4;
        int c = (chunk & 15) << 3;
        *(uint4*)(pA + r * STRB + c * 2) =
            *(const uint4*)&g_xb[(size_t)(rowBase + r) * DD + c];
        *(uint4*)(pB + r * STRB + c * 2) =
            *(const uint4*)&g_xb[(size_t)(colBase + r) * DD + c];
    }
    if (tid < TILE) { rsum[tid] = 0.0f; csum[tid] = 0.0f; }
    __syncthreads();

    uint32_t lrow = lane & 15;
    uint32_t lcol = (lane >> 4) << 4;
    uint32_t aAddr = smem_u32(pA) + (warp_m * 32 + lrow) * STRB + lcol;
    uint32_t bAddr = smem_u32(pB) + (warp_n * 64 + lrow) * STRB + lcol;

    float acc[2][8][4];
#pragma unroll
    for (int mf = 0; mf < 2; mf++)
#pragma unroll
        for (int nf = 0; nf < 8; nf++)
#pragma unroll
            for (int e = 0; e < 4; e++) acc[mf][nf][e] = 0.0f;

#pragma unroll
    for (int kk = 0; kk < 8; kk++) {
        uint32_t ka = kk * 32;
        uint32_t a[2][4];
        ldm_x4(a[0][0], a[0][1], a[0][2], a[0][3], aAddr + ka);
        ldm_x4(a[1][0], a[1][1], a[1][2], a[1][3], aAddr + 16 * STRB + ka);
        uint32_t br[4][4];
#pragma unroll
        for (int nb = 0; nb < 4; nb++)
            ldm_x4(br[nb][0], br[nb][1], br[nb][2], br[nb][3],
                   bAddr + nb * 16 * STRB + ka);
#pragma unroll
        for (int mf = 0; mf < 2; mf++)
#pragma unroll
            for (int nf = 0; nf < 8; nf++) {
                int nb = nf >> 1, odd = nf & 1;
                mma16816(acc[mf][nf], a[mf], br[nb][odd], br[nb][odd + 2]);
            }
    }

    // Epilogue. c-frag: lane (q=lane>>2, rm=lane&3) holds rows q,q+8 x cols 2rm,2rm+1.
    int q = lane >> 2, rm = lane & 3;
    float csA[8], csB[8];   // column partial sums (cols 2rm / 2rm+1 per nf)
#pragma unroll
    for (int nf = 0; nf < 8; nf++) { csA[nf] = 0.0f; csB[nf] = 0.0f; }

#pragma unroll
    for (int mf = 0; mf < 2; mf++) {
        int r0  = warp_m * 32 + mf * 16 + q;
        int gr0 = rowBase + r0, gr1 = gr0 + 8;
        float s0 = 0.0f, s1 = 0.0f;
#pragma unroll
        for (int nf = 0; nf < 8; nf++) {
            int gc = colBase + warp_n * 64 + nf * 8 + rm * 2;
            float e0 = __expf(acc[mf][nf][0] * AINV);
            float e1 = __expf(acc[mf][nf][1] * AINV);
            float e2 = __expf(acc[mf][nf][2] * AINV);
            float e3 = __expf(acc[mf][nf][3] * AINV);
            if (diag) {            // only diagonal tiles can hit gr == gc
                if (gr0 == gc)     e0 = 0.0f;
                if (gr0 == gc + 1) e1 = 0.0f;
                if (gr1 == gc)     e2 = 0.0f;
                if (gr1 == gc + 1) e3 = 0.0f;
            }
            s0 += e0 + e1;
            s1 += e2 + e3;
            csA[nf] += e0 + e2;
            csB[nf] += e1 + e3;
        }
        s0 += __shfl_xor_sync(0xffffffffu, s0, 1);
        s0 += __shfl_xor_sync(0xffffffffu, s0, 2);
        s1 += __shfl_xor_sync(0xffffffffu, s1, 1);
        s1 += __shfl_xor_sync(0xffffffffu, s1, 2);
        if (rm == 0) {
            atomicAdd(&rsum[r0], s0);
            atomicAdd(&rsum[r0 + 8], s1);
        }
    }

    if (!diag) {
        // Reduce column sums over q (lanes stride 4,8,16), then across warp_m.
#pragma unroll
        for (int nf = 0; nf < 8; nf++) {
#pragma unroll
            for (int o = 4; o <= 16; o <<= 1) {
                csA[nf] += __shfl_xor_sync(0xffffffffu, csA[nf], o);
                csB[nf] += __shfl_xor_sync(0xffffffffu, csB[nf], o);
            }
        }
        if (q == 0) {   // lanes 0-3 hold totals for cols 2rm, 2rm+1 per nf
#pragma unroll
            for (int nf = 0; nf < 8; nf++) {
                int c = warp_n * 64 + nf * 8 + rm * 2;
                atomicAdd(&csum[c],     csA[nf]);
                atomicAdd(&csum[c + 1], csB[nf]);
            }
        }
    }
    __syncthreads();

    if (tid < TILE) {
        atomicAdd(&g_rowsum[rowBase + tid], rsum[tid]);
        if (!diag) atomicAdd(&g_rowsum[colBase + tid], csum[tid]);
    }
}

// ---------------------------------------------------------------------------
__global__ void finalize_kernel(float* out) {
    int i    = blockIdx.x * blockDim.x + threadIdx.x;
    int lane = threadIdx.x & 31;
    float l = 0.0f;
    if (i < NROWS)
        l = AINV * g_tdot[i >> 1] - logf(g_rowsum[i]);
#pragma unroll
    for (int o = 16; o; o >>= 1) l += __shfl_xor_sync(0xffffffffu, l, o);
    if (lane == 0) atomicAdd(out, -l * (1.0f / NROWS));
}

// ---------------------------------------------------------------------------
extern "C" void kernel_launch(void* const* d_in, const int* in_sizes, int n_in,
                              void* d_out, int out_size) {
    const float* in = (const float*)d_in[0];
    float* out = (float*)d_out;
    (void)in_sizes; (void)n_in; (void)out_size;

    int dynBytes = 2 * 128 * STRB;   // 69632
    (void)cudaFuncSetAttribute(expsum_mma_kernel,
                               cudaFuncAttributeMaxDynamicSharedMemorySize,
                               dynBytes);

    zero_kernel<<<NROWS / 256, 256>>>(out);
    normalize_kernel<<<NROWS / 2 / 8, 256>>>(in);
    expsum_mma_kernel<<<NTILES, 256, dynBytes>>>();
    finalize_kernel<<<NROWS / 256, 256>>>(out);
}